// round 1
// baseline (speedup 1.0000x reference)
#include <cuda_runtime.h>
#include <cuda_bf16.h>

// Problem constants (from reference setup_inputs)
#define BATCH 256
#define NRET  100      // stored retrieval slots per row
#define RNUM  80       // RETRIEVAL_NUM actually used
#define DIM   768
#define THRESH 0.5f

// Output layout: concatenation of the 6 reference outputs, each row-major f32:
//   vis_packed [B,80,768]   offset 0
//   txt_packed [B,80,768]   offset B*80*768
//   text_mask  [B,81]       offset 2*B*80*768
//   img_mask   [B,81]       +B*81
//   rr_mod     [B,80]       +B*81
//   labels     [B,80]       +B*80

__global__ __launch_bounds__(DIM / 4)
void rrcp_pack_kernel(const float* __restrict__ vis,
                      const float* __restrict__ txt,
                      const float* __restrict__ labels,
                      const float* __restrict__ rr,
                      float* __restrict__ out)
{
    const int j = blockIdx.x;   // packed slot 0..79
    const int b = blockIdx.y;   // batch row 0..255
    const int t = threadIdx.x;  // 0..191

    __shared__ int s_src;
    __shared__ int s_cnt;

    if (t == 0) {
        const float* r = rr + (size_t)b * NRET;
        int cnt = 0, src = -1;
        #pragma unroll
        for (int i = 0; i < RNUM; i++) {
            if (r[i] > THRESH) {          // binary selection, stable order
                if (cnt == j) src = i;
                cnt++;
            }
        }
        s_src = src;
        s_cnt = cnt;
    }
    __syncthreads();
    const int src = s_src;

    // Packed feature copies: 192 float4 per 768-float row
    const size_t row_f4 = (size_t)(b * RNUM + j) * (DIM / 4);
    float4* __restrict__ ov = reinterpret_cast<float4*>(out) + row_f4;
    float4* __restrict__ ot = reinterpret_cast<float4*>(out + (size_t)BATCH * RNUM * DIM) + row_f4;

    if (src >= 0) {
        const float4* __restrict__ sv =
            reinterpret_cast<const float4*>(vis + ((size_t)b * NRET + src) * DIM);
        const float4* __restrict__ st =
            reinterpret_cast<const float4*>(txt + ((size_t)b * NRET + src) * DIM);
        ov[t] = sv[t];
        ot[t] = st[t];
    } else {
        const float4 z = make_float4(0.f, 0.f, 0.f, 0.f);
        ov[t] = z;   // slot beyond count: pure zero store
        ot[t] = z;
    }

    // Small tail outputs: emitted once per batch row by the j==0 block
    if (j == 0) {
        const int cnt = s_cnt;
        float* __restrict__ text_mask = out + 2 * (size_t)BATCH * RNUM * DIM;
        float* __restrict__ img_mask  = text_mask + (size_t)BATCH * (RNUM + 1);
        float* __restrict__ rr_mod    = img_mask  + (size_t)BATCH * (RNUM + 1);
        float* __restrict__ lab_out   = rr_mod    + (size_t)BATCH * RNUM;

        if (t <= RNUM) {
            const float m = (t <= cnt) ? 1.0f : 0.0f;
            text_mask[b * (RNUM + 1) + t] = m;
            img_mask [b * (RNUM + 1) + t] = (b == BATCH - 1) ? m : 1.0f;
        }
        if (t < RNUM) {
            const float v = rr[(size_t)b * NRET + t];
            float m = (v < THRESH) ? 0.0f : v;    // rr_mod = where(rr<0.5, 0, rr)
            if (t == 0) {
                // zero_rows: every rr_mod element in this row is exactly 0,
                // i.e. all rr[b, :80] < 0.5  (rr==0.5 keeps value 0.5 != 0)
                bool zr = true;
                const float* r = rr + (size_t)b * NRET;
                #pragma unroll
                for (int i = 0; i < RNUM; i++) zr = zr && (r[i] < THRESH);
                if (zr) m = 1.0f;
            }
            rr_mod [b * RNUM + t] = m;
            lab_out[b * RNUM + t] = labels[(size_t)b * NRET + t];
        }
    }
}

extern "C" void kernel_launch(void* const* d_in, const int* in_sizes, int n_in,
                              void* d_out, int out_size)
{
    // metadata order:
    // 0: mean_pooling_vec (unused)
    // 1: merge_text_vec   (unused)
    // 2: retrieved_visual_feature_embedding_cls [B,100,1,768]
    // 3: retrieved_textual_feature_embedding    [B,100,1,768]
    // 4: retrieved_label_list [B,100]
    // 5: RRCP                 [B,100]
    const float* vis    = (const float*)d_in[2];
    const float* txt    = (const float*)d_in[3];
    const float* labels = (const float*)d_in[4];
    const float* rr     = (const float*)d_in[5];
    float* out = (float*)d_out;

    dim3 grid(RNUM, BATCH);
    rrcp_pack_kernel<<<grid, DIM / 4>>>(vis, txt, labels, rr, out);
}

// round 3
// speedup vs baseline: 1.1565x; 1.1565x over previous
#include <cuda_runtime.h>
#include <cuda_bf16.h>

#define BATCH 256
#define NRET  100      // stored retrieval slots per row
#define RNUM  80       // RETRIEVAL_NUM actually used
#define DIM   768
#define THRESH 0.5f

// Scratch: per-(b, packed-slot) source index, -1 for zero-fill slots.
__device__ int d_src[BATCH * RNUM];

// ---------------------------------------------------------------------------
// Kernel A: build the permutation table + all small outputs. One block per
// batch row; warp 0 does a ballot-based stable compaction of the 80 flags.
// ---------------------------------------------------------------------------
__global__ __launch_bounds__(128)
void rrcp_index_kernel(const float* __restrict__ labels,
                       const float* __restrict__ rr,
                       float* __restrict__ out)
{
    const int b = blockIdx.x;
    const int t = threadIdx.x;
    const int lane = t & 31;

    __shared__ int s_cnt;
    __shared__ int s_anyge;   // any rr[b,i] >= 0.5 ?

    if (t < 32) {
        int base = 0;
        unsigned anyge = 0;
        #pragma unroll
        for (int chunk = 0; chunk < 3; chunk++) {
            const int i = chunk * 32 + lane;
            float v = (i < RNUM) ? __ldg(&rr[(size_t)b * NRET + i]) : 0.0f;
            bool f = (i < RNUM) && (v > THRESH);
            unsigned m = __ballot_sync(0xffffffffu, f);
            anyge |= __ballot_sync(0xffffffffu, (i < RNUM) && (v >= THRESH));
            if (f)
                d_src[b * RNUM + base + __popc(m & ((1u << lane) - 1u))] = i;
            base += __popc(m);
        }
        if (lane == 0) { s_cnt = base; s_anyge = (anyge != 0); }
    }
    __syncthreads();
    const int cnt = s_cnt;

    // Fill unused packed slots with -1
    for (int p = cnt + t; p < RNUM; p += 128)
        d_src[b * RNUM + p] = -1;

    // Small outputs
    float* __restrict__ text_mask = out + 2 * (size_t)BATCH * RNUM * DIM;
    float* __restrict__ img_mask  = text_mask + (size_t)BATCH * (RNUM + 1);
    float* __restrict__ rr_mod    = img_mask  + (size_t)BATCH * (RNUM + 1);
    float* __restrict__ lab_out   = rr_mod    + (size_t)BATCH * RNUM;

    if (t <= RNUM) {
        const float m = (t <= cnt) ? 1.0f : 0.0f;
        text_mask[b * (RNUM + 1) + t] = m;
        img_mask [b * (RNUM + 1) + t] = (b == BATCH - 1) ? m : 1.0f;
    }
    if (t < RNUM) {
        const float v = __ldg(&rr[(size_t)b * NRET + t]);
        float m = (v < THRESH) ? 0.0f : v;          // where(rr<0.5, 0, rr)
        if (t == 0 && !s_anyge) m = 1.0f;           // zero-row fix at col 0
        rr_mod [b * RNUM + t] = m;
        lab_out[b * RNUM + t] = labels[(size_t)b * NRET + t];
    }
}

// ---------------------------------------------------------------------------
// Kernel B: pure streaming copy. One block per (b, packed slot). No scan, no
// barrier — one broadcast index load, then 2x LDG.128 + 2x STG.128 per thread.
// Stores use evict-first (.cs) so the write stream doesn't flush the
// L2-resident source rows.
// ---------------------------------------------------------------------------
__global__ __launch_bounds__(DIM / 4)
void rrcp_copy_kernel(const float* __restrict__ vis,
                      const float* __restrict__ txt,
                      float* __restrict__ out)
{
    const int j = blockIdx.x;   // packed slot 0..79
    const int b = blockIdx.y;   // batch row
    const int t = threadIdx.x;  // 0..191

    const int src = __ldg(&d_src[b * RNUM + j]);   // uniform broadcast

    const size_t row_f4 = (size_t)(b * RNUM + j) * (DIM / 4);
    float4* __restrict__ ov = reinterpret_cast<float4*>(out) + row_f4;
    float4* __restrict__ ot = ov + (size_t)BATCH * RNUM * (DIM / 4);

    if (src >= 0) {
        const float4* __restrict__ sv =
            reinterpret_cast<const float4*>(vis + ((size_t)b * NRET + src) * DIM);
        const float4* __restrict__ st =
            reinterpret_cast<const float4*>(txt + ((size_t)b * NRET + src) * DIM);
        float4 a = __ldg(&sv[t]);       // two independent loads, MLP=2
        float4 c = __ldg(&st[t]);
        __stcs(&ov[t], a);
        __stcs(&ot[t], c);
    } else {
        const float4 z = make_float4(0.f, 0.f, 0.f, 0.f);
        __stcs(&ov[t], z);              // pure zero store, no load
        __stcs(&ot[t], z);
    }
}

extern "C" void kernel_launch(void* const* d_in, const int* in_sizes, int n_in,
                              void* d_out, int out_size)
{
    // metadata order:
    // 0: mean_pooling_vec (unused)
    // 1: merge_text_vec   (unused)
    // 2: retrieved_visual_feature_embedding_cls [B,100,1,768]
    // 3: retrieved_textual_feature_embedding    [B,100,1,768]
    // 4: retrieved_label_list [B,100]
    // 5: RRCP                 [B,100]
    const float* vis    = (const float*)d_in[2];
    const float* txt    = (const float*)d_in[3];
    const float* labels = (const float*)d_in[4];
    const float* rr     = (const float*)d_in[5];
    float* out = (float*)d_out;

    rrcp_index_kernel<<<BATCH, 128>>>(labels, rr, out);
    dim3 grid(RNUM, BATCH);
    rrcp_copy_kernel<<<grid, DIM / 4>>>(vis, txt, out);
}

// round 4
// speedup vs baseline: 1.2143x; 1.0500x over previous
#include <cuda_runtime.h>
#include <cuda_bf16.h>

#define BATCH 256
#define NRET  100      // stored retrieval slots per row
#define RNUM  80       // RETRIEVAL_NUM actually used
#define DIM   768
#define DF4   (DIM / 4)
#define THRESH 0.5f

#define SLICES    8
#define SLOTS_PER (RNUM / SLICES)   // 10 packed slots per block

// Output layout (concatenation, all f32 row-major):
//   vis_packed [B,80,768] | txt_packed [B,80,768] |
//   text_mask [B,81] | img_mask [B,81] | rr_mod [B,80] | labels [B,80]

__global__ __launch_bounds__(192)
void rrcp_fused_kernel(const float* __restrict__ vis,
                       const float* __restrict__ txt,
                       const float* __restrict__ labels,
                       const float* __restrict__ rr,
                       float* __restrict__ out)
{
    const int slice = blockIdx.x;           // 0..7
    const int b     = blockIdx.y;           // 0..255
    const int t     = threadIdx.x;          // 0..191
    const int j0    = slice * SLOTS_PER;

    __shared__ int s_src[SLOTS_PER];
    __shared__ int s_cnt;
    __shared__ int s_anyge;

    // ---- warp 0: stable compaction scan over the 80 rr flags ----
    if (t < 32) {
        const int lane = t;
        if (lane < SLOTS_PER) s_src[lane] = -1;
        __syncwarp();

        int base = 0;
        unsigned anyge = 0;
        #pragma unroll
        for (int chunk = 0; chunk < 3; chunk++) {
            const int i = chunk * 32 + lane;
            const float v = (i < RNUM) ? __ldg(&rr[(size_t)b * NRET + i]) : 0.0f;
            const bool f = (i < RNUM) && (v > THRESH);
            const unsigned m = __ballot_sync(0xffffffffu, f);
            anyge |= __ballot_sync(0xffffffffu, (i < RNUM) && (v >= THRESH));
            const int pos = base + __popc(m & ((1u << lane) - 1u));
            if (f && pos >= j0 && pos < j0 + SLOTS_PER)
                s_src[pos - j0] = i;       // source slot for packed position 'pos'
            base += __popc(m);
        }
        if (lane == 0) { s_cnt = base; s_anyge = (anyge != 0); }
    }
    __syncthreads();

    // ---- coarsened copy: 10 packed slots per block ----
    const size_t out_row0 = ((size_t)b * RNUM + j0) * DF4;
    float4* __restrict__ ov = reinterpret_cast<float4*>(out) + out_row0;
    float4* __restrict__ ot = ov + (size_t)BATCH * RNUM * DF4;
    const float4* __restrict__ vbase =
        reinterpret_cast<const float4*>(vis) + (size_t)b * NRET * DF4;
    const float4* __restrict__ tbase =
        reinterpret_cast<const float4*>(txt) + (size_t)b * NRET * DF4;

    #pragma unroll 2
    for (int k = 0; k < SLOTS_PER; k++) {
        const int src = s_src[k];
        float4 a, c;
        if (src >= 0) {
            a = __ldg(&vbase[(size_t)src * DF4 + t]);
            c = __ldg(&tbase[(size_t)src * DF4 + t]);
        } else {
            a = make_float4(0.f, 0.f, 0.f, 0.f);
            c = a;
        }
        __stcs(&ov[(size_t)k * DF4 + t], a);   // evict-first: keep sources L2-hot
        __stcs(&ot[(size_t)k * DF4 + t], c);
    }

    // ---- slice 0 emits the small outputs for this batch row ----
    if (slice == 0) {
        const int cnt = s_cnt;
        float* __restrict__ text_mask = out + 2 * (size_t)BATCH * RNUM * DIM;
        float* __restrict__ img_mask  = text_mask + (size_t)BATCH * (RNUM + 1);
        float* __restrict__ rr_mod    = img_mask  + (size_t)BATCH * (RNUM + 1);
        float* __restrict__ lab_out   = rr_mod    + (size_t)BATCH * RNUM;

        if (t <= RNUM) {
            const float m = (t <= cnt) ? 1.0f : 0.0f;
            text_mask[b * (RNUM + 1) + t] = m;
            img_mask [b * (RNUM + 1) + t] = (b == BATCH - 1) ? m : 1.0f;
        }
        if (t < RNUM) {
            const float v = __ldg(&rr[(size_t)b * NRET + t]);
            float m = (v < THRESH) ? 0.0f : v;     // where(rr<0.5, 0, rr)
            if (t == 0 && !s_anyge) m = 1.0f;      // all-zero row fix at col 0
            rr_mod [b * RNUM + t] = m;
            lab_out[b * RNUM + t] = labels[(size_t)b * NRET + t];
        }
    }
}

extern "C" void kernel_launch(void* const* d_in, const int* in_sizes, int n_in,
                              void* d_out, int out_size)
{
    // metadata order:
    // 0: mean_pooling_vec (unused)
    // 1: merge_text_vec   (unused)
    // 2: retrieved_visual_feature_embedding_cls [B,100,1,768]
    // 3: retrieved_textual_feature_embedding    [B,100,1,768]
    // 4: retrieved_label_list [B,100]
    // 5: RRCP                 [B,100]
    const float* vis    = (const float*)d_in[2];
    const float* txt    = (const float*)d_in[3];
    const float* labels = (const float*)d_in[4];
    const float* rr     = (const float*)d_in[5];
    float* out = (float*)d_out;

    dim3 grid(SLICES, BATCH);
    rrcp_fused_kernel<<<grid, 192>>>(vis, txt, labels, rr, out);
}